// round 9
// baseline (speedup 1.0000x reference)
#include <cuda_runtime.h>
#include <cuda_fp16.h>
#include <cstdint>

#define CCH 256
#define TLEN 8192
#define BSZ 4
#define NLAYER 10
#define STGB 40960     // per stage: W 32KB (hi+lo) + Xhi 4KB + Xlo 4KB
#define SMEMB 81920    // 2 stages -> 2 CTAs/SM
typedef __half fp16;

// ---------- static scratch ----------
__device__ fp16 g_xh[(size_t)BSZ * TLEN * CCH];
__device__ fp16 g_xl[(size_t)BSZ * TLEN * CCH];
__device__ fp16 g_hh[(size_t)BSZ * TLEN * CCH];
__device__ fp16 g_hl[(size_t)BSZ * TLEN * CCH];
__device__ float g_xcm[(size_t)BSZ * CCH * TLEN];
__device__ fp16 g_wcA[(size_t)NLAYER * 2 * 24 * 2 * 8192];  // [l][g][chunk32][half][256r][32k] SW64
__device__ fp16 g_woA[(size_t)NLAYER * 8 * 2 * 8192];       // [l][chunk32][half][256r][32k] SW64

// ---------- helpers ----------
__device__ __forceinline__ uint32_t s2u(const void* p) {
    uint32_t a;
    asm("{ .reg .u64 t; cvta.to.shared.u64 t, %1; cvt.u32.u64 %0, t; }" : "=r"(a) : "l"(p));
    return a;
}
__device__ __forceinline__ void cpa16(uint32_t d, const void* s) {
    asm volatile("cp.async.cg.shared.global [%0], [%1], 16;" :: "r"(d), "l"(s));
}
__device__ __forceinline__ void cpa16z(uint32_t d, const void* s, uint32_t n) {
    asm volatile("cp.async.cg.shared.global [%0], [%1], 16, %2;" :: "r"(d), "l"(s), "r"(n));
}
#define CPC() asm volatile("cp.async.commit_group;" ::: "memory")
__device__ __forceinline__ uint32_t swz64(uint32_t b) { return b ^ ((b >> 3) & 0x30); }
__device__ __forceinline__ float sigf(float x) {
    return __fdividef(1.0f, 1.0f + __expf(-x));
}
__device__ __forceinline__ void ldsm4(uint32_t& r0, uint32_t& r1, uint32_t& r2, uint32_t& r3, uint32_t a) {
    asm volatile("ldmatrix.sync.aligned.m8n8.x4.shared.b16 {%0,%1,%2,%3}, [%4];"
                 : "=r"(r0), "=r"(r1), "=r"(r2), "=r"(r3) : "r"(a));
}
// main term: f32 accumulate
__device__ __forceinline__ void mma_f32(float* c, const uint32_t* a, uint32_t b0, uint32_t b1) {
    asm volatile(
        "mma.sync.aligned.m16n8k16.row.col.f32.f16.f16.f32 "
        "{%0,%1,%2,%3},{%4,%5,%6,%7},{%8,%9},{%0,%1,%2,%3};"
        : "+f"(c[0]), "+f"(c[1]), "+f"(c[2]), "+f"(c[3])
        : "r"(a[0]), "r"(a[1]), "r"(a[2]), "r"(a[3]), "r"(b0), "r"(b1));
}
// correction terms: f16 accumulate (packed f16x2 in 2 regs)
__device__ __forceinline__ void mma_f16(uint32_t* c, const uint32_t* a, uint32_t b0, uint32_t b1) {
    asm volatile(
        "mma.sync.aligned.m16n8k16.row.col.f16.f16.f16.f16 "
        "{%0,%1},{%2,%3,%4,%5},{%6,%7},{%0,%1};"
        : "+r"(c[0]), "+r"(c[1])
        : "r"(a[0]), "r"(a[1]), "r"(a[2]), "r"(a[3]), "r"(b0), "r"(b1));
}

// ---------- prep kernels ----------
__global__ void prep_x(const float* __restrict__ in, fp16* __restrict__ xh, fp16* __restrict__ xl) {
    __shared__ float tl[32][33];
    int t0 = blockIdx.x * 32, c0 = blockIdx.y * 32, b = blockIdx.z;
    int tx = threadIdx.x, ty = threadIdx.y;
    #pragma unroll
    for (int r = 0; r < 4; ++r)
        tl[ty + r * 8][tx] = in[((size_t)b * CCH + c0 + ty + r * 8) * TLEN + t0 + tx];
    __syncthreads();
    #pragma unroll
    for (int r = 0; r < 4; ++r) {
        int t = t0 + ty + r * 8;
        float v = tl[tx][ty + r * 8];
        fp16 hi = __float2half(v);
        size_t o = ((size_t)b * TLEN + t) * CCH + c0 + tx;
        xh[o] = hi; xl[o] = __float2half(v - __half2float(hi));
    }
}

__global__ void prep_wc(const float* __restrict__ w, fp16* __restrict__ wa) {
    size_t i = (size_t)blockIdx.x * 256 + threadIdx.x;
    if (i >= (size_t)NLAYER * 2 * 24 * 2 * 8192) return;
    int e = (int)(i & 8191);
    int tile = (int)(i >> 13);
    int half = tile & 1;
    int chunk = (tile >> 1) % 24;
    int lg = (tile >> 1) / 24;
    int g = lg & 1, l = lg >> 1;
    int row = e >> 5, k = e & 31;
    int o = (row < 128) ? g * 128 + row : 128 + g * 128 + row;
    int tap = chunk >> 3;
    int c = (chunk & 7) * 32 + k;
    float v = w[(((size_t)l * 512 + o) * 256 + c) * 3 + tap];
    fp16 hi = __float2half(v);
    fp16 val = half ? __float2half(v - __half2float(hi)) : hi;
    wa[(size_t)tile * 8192 + (swz64(row * 64 + k * 2) >> 1)] = val;
}

__global__ void prep_wo(const float* __restrict__ w, fp16* __restrict__ wa) {
    size_t i = (size_t)blockIdx.x * 256 + threadIdx.x;
    if (i >= (size_t)NLAYER * 8 * 2 * 8192) return;
    int e = (int)(i & 8191);
    int tile = (int)(i >> 13);
    int half = tile & 1;
    int chunk = (tile >> 1) & 7;
    int l = (tile >> 1) >> 3;
    int row = e >> 5, k = e & 31;
    int c = chunk * 32 + k;
    float v = w[((size_t)l * 256 + row) * 256 + c];
    fp16 hi = __float2half(v);
    fp16 val = half ? __float2half(v - __half2float(hi)) : hi;
    wa[(size_t)tile * 8192 + (swz64(row * 64 + k * 2) >> 1)] = val;
}

// ---------- per-chunk compute: warp tile 32t x 64o, K=32 ----------
__device__ __forceinline__ void compute_stage(
    uint32_t Wb, uint32_t Xb, int tg, int oq, int lane,
    float acc[2][8][4], uint32_t acc16[2][8][2])
{
    #pragma unroll
    for (int kk = 0; kk < 2; ++kk) {
        uint32_t Ah[2][4], Al[2][4];
        int aseg = 2 * kk + (lane >> 4);
        #pragma unroll
        for (int mt = 0; mt < 2; ++mt) {
            int r = tg * 32 + mt * 16 + (lane & 15);
            uint32_t aa = Xb + r * 64 + ((uint32_t)(aseg ^ ((r >> 1) & 3)) << 4);
            ldsm4(Ah[mt][0], Ah[mt][1], Ah[mt][2], Ah[mt][3], aa);
            ldsm4(Al[mt][0], Al[mt][1], Al[mt][2], Al[mt][3], aa + 4096);
        }
        #pragma unroll
        for (int np = 0; np < 4; ++np) {
            int br = oq * 64 + np * 16 + ((lane >> 4) << 3) + (lane & 7);
            int bseg = 2 * kk + ((lane >> 3) & 1);
            uint32_t ba = Wb + br * 64 + ((uint32_t)(bseg ^ ((br >> 1) & 3)) << 4);
            uint32_t bh0, bh1, bh2, bh3, bl0, bl1, bl2, bl3;
            ldsm4(bh0, bh1, bh2, bh3, ba);
            ldsm4(bl0, bl1, bl2, bl3, ba + 16384);
            #pragma unroll
            for (int mt = 0; mt < 2; ++mt) {
                mma_f32(acc[mt][2 * np],     Ah[mt], bh0, bh1);
                mma_f32(acc[mt][2 * np + 1], Ah[mt], bh2, bh3);
                mma_f16(acc16[mt][2 * np],     Al[mt], bh0, bh1);
                mma_f16(acc16[mt][2 * np + 1], Al[mt], bh2, bh3);
                mma_f16(acc16[mt][2 * np],     Ah[mt], bl0, bl1);
                mma_f16(acc16[mt][2 * np + 1], Ah[mt], bl2, bl3);
            }
        }
    }
}

__device__ __forceinline__ void merge_corr(float acc[2][8][4], uint32_t acc16[2][8][2]) {
    #pragma unroll
    for (int mt = 0; mt < 2; ++mt)
        #pragma unroll
        for (int nt = 0; nt < 8; ++nt) {
            float2 p0 = __half22float2(*(__half2*)&acc16[mt][nt][0]);
            float2 p1 = __half22float2(*(__half2*)&acc16[mt][nt][1]);
            acc[mt][nt][0] += p0.x;
            acc[mt][nt][1] += p0.y;
            acc[mt][nt][2] += p1.x;
            acc[mt][nt][3] += p1.y;
        }
}

// ---------- conv layer kernel: CTA = 64t x 256o, 24 K-chunks of 32 ----------
__global__ __launch_bounds__(256, 2) void conv_k(
    const fp16* __restrict__ xh, const fp16* __restrict__ xl,
    const fp16* __restrict__ wA, const float* __restrict__ bconv,
    const float* __restrict__ xres, float* __restrict__ skip,
    fp16* __restrict__ hh, fp16* __restrict__ hl,
    float* __restrict__ xout, int dil, int last)
{
    extern __shared__ char sm[];
    uint32_t sbd = s2u(sm);
    int tid = threadIdx.x, lane = tid & 31, wid = tid >> 5;
    int g = blockIdx.y;
    int b = blockIdx.x >> 7, t0 = (blockIdx.x & 127) << 6;
    int tg = wid & 1, oq = wid >> 1;
    const char* xhB = (const char*)xh;
    const char* xlB = (const char*)xl;

    auto load_chunk = [&](int c, int s) {
        uint32_t SS = sbd + s * STGB;
        const char* wsrc = (const char*)(wA + ((size_t)(g * 24 + c)) * 16384);
        #pragma unroll
        for (int it = 0; it < 8; ++it) {
            uint32_t off = it * 4096 + tid * 16;
            cpa16(SS + off, wsrc + off);
        }
        int tap = c >> 3, kq = c & 7;
        int tt = tid >> 2, sg = tid & 3;
        int ts = t0 + tt - dil * (2 - tap);
        uint32_t pr = ts >= 0 ? 16u : 0u;
        size_t gb = (size_t)(b * TLEN + (ts < 0 ? 0 : ts)) * 512 + kq * 64;
        uint32_t dst = SS + 32768 + tt * 64 + ((uint32_t)(sg ^ ((tt >> 1) & 3)) << 4);
        cpa16z(dst, xhB + gb + sg * 16, pr);
        cpa16z(dst + 4096, xlB + gb + sg * 16, pr);
        CPC();
    };

    float acc[2][8][4];
    uint32_t acc16[2][8][2];
    #pragma unroll
    for (int a = 0; a < 2; ++a)
        #pragma unroll
        for (int n = 0; n < 8; ++n) {
            #pragma unroll
            for (int q = 0; q < 4; ++q) acc[a][n][q] = 0.0f;
            acc16[a][n][0] = 0u; acc16[a][n][1] = 0u;
        }

    load_chunk(0, 0);
    for (int c = 0; c < 24; ++c) {
        int s = c & 1;
        asm volatile("cp.async.wait_group 0;" ::: "memory");
        __syncthreads();
        if (c + 1 < 24) load_chunk(c + 1, 1 - s);
        compute_stage(sbd + s * STGB, sbd + s * STGB + 32768, tg, oq, lane, acc, acc16);
    }
    merge_corr(acc, acc16);
    __syncthreads();

    // ---- epilogue ----
    float* zb = (float*)sm;
    #pragma unroll
    for (int mt = 0; mt < 2; ++mt)
        #pragma unroll
        for (int nt = 0; nt < 8; ++nt) {
            int t = tg * 32 + mt * 16 + (lane >> 2);
            int o = oq * 64 + nt * 8 + (lane & 3) * 2;
            *(float2*)&zb[t * 260 + o]       = make_float2(acc[mt][nt][0], acc[mt][nt][1]);
            *(float2*)&zb[(t + 8) * 260 + o] = make_float2(acc[mt][nt][2], acc[mt][nt][3]);
        }
    __syncthreads();
    for (int i = tid; i < 64 * 32; i += 256) {
        int t = i >> 5, c0 = (i & 31) * 4;
        #pragma unroll
        for (int j = 0; j < 4; ++j) {
            float zt = zb[t * 260 + c0 + j];
            float zs = zb[t * 260 + 128 + c0 + j];
            float h = tanhf(zt + bconv[g * 128 + c0 + j]) *
                      sigf(zs + bconv[256 + g * 128 + c0 + j]);
            zb[t * 260 + c0 + j] = h;
        }
    }
    __syncthreads();
    for (int i = tid; i < 128 * 16; i += 256) {
        int o = i >> 4, sg = i & 15, t = sg * 4;
        float4 v;
        v.x = zb[(t + 0) * 260 + o];
        v.y = zb[(t + 1) * 260 + o];
        v.z = zb[(t + 2) * 260 + o];
        v.w = zb[(t + 3) * 260 + o];
        size_t go = ((size_t)(b * 256) + g * 128 + o) * TLEN + t0 + t;
        *(float4*)(skip + go) = v;
        if (last) {
            float4 xr = *(const float4*)(xres + go);
            float4 ov = make_float4(v.x + xr.x, v.y + xr.y, v.z + xr.z, v.w + xr.w);
            *(float4*)(xout + go) = ov;
        }
    }
    if (!last) {
        for (int i = tid; i < 64 * 32; i += 256) {
            int t = i >> 5, c0 = (i & 31) * 4;
            float v0 = zb[t * 260 + c0], v1 = zb[t * 260 + c0 + 1];
            float v2 = zb[t * 260 + c0 + 2], v3 = zb[t * 260 + c0 + 3];
            fp16 h0 = __float2half(v0), h1 = __float2half(v1);
            fp16 h2 = __float2half(v2), h3 = __float2half(v3);
            size_t gi = ((size_t)(b * TLEN) + t0 + t) * CCH + g * 128 + c0;
            ((__half2*)(hh + gi))[0] = __halves2half2(h0, h1);
            ((__half2*)(hh + gi))[1] = __halves2half2(h2, h3);
            fp16 l0 = __float2half(v0 - __half2float(h0));
            fp16 l1 = __float2half(v1 - __half2float(h1));
            fp16 l2 = __float2half(v2 - __half2float(h2));
            fp16 l3 = __float2half(v3 - __half2float(h3));
            ((__half2*)(hl + gi))[0] = __halves2half2(l0, l1);
            ((__half2*)(hl + gi))[1] = __halves2half2(l2, l3);
        }
    }
}

// ---------- 1x1 + residual layer: CTA = 64t x 256o, 8 K-chunks of 32 ----------
__global__ __launch_bounds__(256, 2) void out_k(
    const fp16* __restrict__ hh, const fp16* __restrict__ hl,
    const fp16* __restrict__ wA, const float* __restrict__ bout,
    const float* __restrict__ xres, float* __restrict__ xcm,
    fp16* __restrict__ xh, fp16* __restrict__ xl)
{
    extern __shared__ char sm[];
    uint32_t sbd = s2u(sm);
    int tid = threadIdx.x, lane = tid & 31, wid = tid >> 5;
    int b = blockIdx.x >> 7, t0 = (blockIdx.x & 127) << 6;
    int tg = wid & 1, oq = wid >> 1;
    const char* hhB = (const char*)hh;
    const char* hlB = (const char*)hl;

    auto load_chunk = [&](int c, int s) {
        uint32_t SS = sbd + s * STGB;
        const char* wsrc = (const char*)(wA + (size_t)c * 16384);
        #pragma unroll
        for (int it = 0; it < 8; ++it) {
            uint32_t off = it * 4096 + tid * 16;
            cpa16(SS + off, wsrc + off);
        }
        int tt = tid >> 2, sg = tid & 3;
        size_t gb = (size_t)(b * TLEN + t0 + tt) * 512 + c * 64;
        uint32_t dst = SS + 32768 + tt * 64 + ((uint32_t)(sg ^ ((tt >> 1) & 3)) << 4);
        cpa16(dst, hhB + gb + sg * 16);
        cpa16(dst + 4096, hlB + gb + sg * 16);
        CPC();
    };

    float acc[2][8][4];
    uint32_t acc16[2][8][2];
    #pragma unroll
    for (int a = 0; a < 2; ++a)
        #pragma unroll
        for (int n = 0; n < 8; ++n) {
            #pragma unroll
            for (int q = 0; q < 4; ++q) acc[a][n][q] = 0.0f;
            acc16[a][n][0] = 0u; acc16[a][n][1] = 0u;
        }

    load_chunk(0, 0);
    for (int c = 0; c < 8; ++c) {
        int s = c & 1;
        asm volatile("cp.async.wait_group 0;" ::: "memory");
        __syncthreads();
        if (c + 1 < 8) load_chunk(c + 1, 1 - s);
        compute_stage(sbd + s * STGB, sbd + s * STGB + 32768, tg, oq, lane, acc, acc16);
    }
    merge_corr(acc, acc16);
    __syncthreads();

    float* zb = (float*)sm;
    #pragma unroll
    for (int mt = 0; mt < 2; ++mt)
        #pragma unroll
        for (int nt = 0; nt < 8; ++nt) {
            int t = tg * 32 + mt * 16 + (lane >> 2);
            int o = oq * 64 + nt * 8 + (lane & 3) * 2;
            *(float2*)&zb[t * 260 + o]       = make_float2(acc[mt][nt][0], acc[mt][nt][1]);
            *(float2*)&zb[(t + 8) * 260 + o] = make_float2(acc[mt][nt][2], acc[mt][nt][3]);
        }
    __syncthreads();
    for (int i = tid; i < 256 * 16; i += 256) {
        int o = i >> 4, sg = i & 15, t = sg * 4;
        size_t go = ((size_t)(b * 256) + o) * TLEN + t0 + t;
        float4 xr = *(const float4*)(xres + go);
        float bo = bout[o];
        float4 v;
        v.x = zb[(t + 0) * 260 + o] + bo + xr.x;
        v.y = zb[(t + 1) * 260 + o] + bo + xr.y;
        v.z = zb[(t + 2) * 260 + o] + bo + xr.z;
        v.w = zb[(t + 3) * 260 + o] + bo + xr.w;
        *(float4*)(xcm + go) = v;
        zb[(t + 0) * 260 + o] = v.x;
        zb[(t + 1) * 260 + o] = v.y;
        zb[(t + 2) * 260 + o] = v.z;
        zb[(t + 3) * 260 + o] = v.w;
    }
    __syncthreads();
    for (int i = tid; i < 64 * 64; i += 256) {
        int t = i >> 6, c0 = (i & 63) * 4;
        float v0 = zb[t * 260 + c0], v1 = zb[t * 260 + c0 + 1];
        float v2 = zb[t * 260 + c0 + 2], v3 = zb[t * 260 + c0 + 3];
        fp16 h0 = __float2half(v0), h1 = __float2half(v1);
        fp16 h2 = __float2half(v2), h3 = __float2half(v3);
        size_t gi = ((size_t)(b * TLEN) + t0 + t) * CCH + c0;
        ((__half2*)(xh + gi))[0] = __halves2half2(h0, h1);
        ((__half2*)(xh + gi))[1] = __halves2half2(h2, h3);
        fp16 l0 = __float2half(v0 - __half2float(h0));
        fp16 l1 = __float2half(v1 - __half2float(h1));
        fp16 l2 = __float2half(v2 - __half2float(h2));
        fp16 l3 = __float2half(v3 - __half2float(h3));
        ((__half2*)(xl + gi))[0] = __halves2half2(l0, l1);
        ((__half2*)(xl + gi))[1] = __halves2half2(l2, l3);
    }
}

// ---------- host ----------
extern "C" void kernel_launch(void* const* d_in, const int* in_sizes, int n_in,
                              void* d_out, int out_size) {
    const float* input = (const float*)d_in[0];
    const float* wconv = (const float*)d_in[1];
    const float* bconv = (const float*)d_in[2];
    const float* wout  = (const float*)d_in[3];
    const float* bout  = (const float*)d_in[4];
    float* out = (float*)d_out;

    fp16 *xh, *xl, *hh, *hl, *wcA, *woA; float* xcm;
    cudaGetSymbolAddress((void**)&xh, g_xh);
    cudaGetSymbolAddress((void**)&xl, g_xl);
    cudaGetSymbolAddress((void**)&hh, g_hh);
    cudaGetSymbolAddress((void**)&hl, g_hl);
    cudaGetSymbolAddress((void**)&xcm, g_xcm);
    cudaGetSymbolAddress((void**)&wcA, g_wcA);
    cudaGetSymbolAddress((void**)&woA, g_woA);

    cudaFuncSetAttribute(conv_k, cudaFuncAttributeMaxDynamicSharedMemorySize, SMEMB);
    cudaFuncSetAttribute(out_k,  cudaFuncAttributeMaxDynamicSharedMemorySize, SMEMB);

    prep_x<<<dim3(TLEN / 32, CCH / 32, BSZ), dim3(32, 8)>>>(input, xh, xl);
    {
        size_t n = (size_t)NLAYER * 2 * 24 * 2 * 8192;
        prep_wc<<<(unsigned)((n + 255) / 256), 256>>>(wconv, wcA);
    }
    {
        size_t n = (size_t)NLAYER * 8 * 2 * 8192;
        prep_wo<<<(unsigned)((n + 255) / 256), 256>>>(wout, woA);
    }

    const size_t XE = (size_t)BSZ * CCH * TLEN;
    const int DIL[NLAYER] = {1, 2, 4, 8, 16, 32, 64, 128, 256, 512};

    for (int l = 0; l < NLAYER; ++l) {
        int last = (l == NLAYER - 1);
        conv_k<<<dim3(512, 2), 256, SMEMB>>>(
            xh, xl, wcA + (size_t)l * 2 * 24 * 2 * 8192, bconv + l * 512,
            xcm, out + XE + (size_t)l * XE, hh, hl, out, DIL[l], last);
        if (!last) {
            out_k<<<512, 256, SMEMB>>>(
                hh, hl, woA + (size_t)l * 8 * 2 * 8192, bout + l * 256,
                (l == 0) ? input : xcm, xcm, xh, xl);
        }
    }
    (void)in_sizes; (void)n_in; (void)out_size;
}

// round 10
// speedup vs baseline: 1.3435x; 1.3435x over previous
#include <cuda_runtime.h>
#include <cuda_fp16.h>
#include <cstdint>

#define CCH 256
#define TLEN 8192
#define BSZ 4
#define NLAYER 10
#define STGB 36864     // per stage: W 32KB (hi+lo) + Xhi 4KB
#define SMEMB 73728    // 2 stages -> 2 CTAs/SM
typedef __half fp16;

// ---------- static scratch ----------
__device__ fp16 g_xh[(size_t)BSZ * TLEN * CCH];
__device__ fp16 g_hh[(size_t)BSZ * TLEN * CCH];
__device__ float g_xcm[(size_t)BSZ * CCH * TLEN];
__device__ fp16 g_wcA[(size_t)NLAYER * 2 * 24 * 2 * 8192];  // [l][g][chunk32][half][256r][32k] SW64
__device__ fp16 g_woA[(size_t)NLAYER * 8 * 2 * 8192];       // [l][chunk32][half][256r][32k] SW64

// ---------- helpers ----------
__device__ __forceinline__ uint32_t s2u(const void* p) {
    uint32_t a;
    asm("{ .reg .u64 t; cvta.to.shared.u64 t, %1; cvt.u32.u64 %0, t; }" : "=r"(a) : "l"(p));
    return a;
}
__device__ __forceinline__ void cpa16(uint32_t d, const void* s) {
    asm volatile("cp.async.cg.shared.global [%0], [%1], 16;" :: "r"(d), "l"(s));
}
__device__ __forceinline__ void cpa16z(uint32_t d, const void* s, uint32_t n) {
    asm volatile("cp.async.cg.shared.global [%0], [%1], 16, %2;" :: "r"(d), "l"(s), "r"(n));
}
#define CPC() asm volatile("cp.async.commit_group;" ::: "memory")
__device__ __forceinline__ uint32_t swz64(uint32_t b) { return b ^ ((b >> 3) & 0x30); }
__device__ __forceinline__ float sigf(float x) {
    return __fdividef(1.0f, 1.0f + __expf(-x));
}
__device__ __forceinline__ void ldsm4(uint32_t& r0, uint32_t& r1, uint32_t& r2, uint32_t& r3, uint32_t a) {
    asm volatile("ldmatrix.sync.aligned.m8n8.x4.shared.b16 {%0,%1,%2,%3}, [%4];"
                 : "=r"(r0), "=r"(r1), "=r"(r2), "=r"(r3) : "r"(a));
}
__device__ __forceinline__ void mma_f32(float* c, const uint32_t* a, uint32_t b0, uint32_t b1) {
    asm volatile(
        "mma.sync.aligned.m16n8k16.row.col.f32.f16.f16.f32 "
        "{%0,%1,%2,%3},{%4,%5,%6,%7},{%8,%9},{%0,%1,%2,%3};"
        : "+f"(c[0]), "+f"(c[1]), "+f"(c[2]), "+f"(c[3])
        : "r"(a[0]), "r"(a[1]), "r"(a[2]), "r"(a[3]), "r"(b0), "r"(b1));
}
__device__ __forceinline__ void mma_f16(uint32_t* c, const uint32_t* a, uint32_t b0, uint32_t b1) {
    asm volatile(
        "mma.sync.aligned.m16n8k16.row.col.f16.f16.f16.f16 "
        "{%0,%1},{%2,%3,%4,%5},{%6,%7},{%0,%1};"
        : "+r"(c[0]), "+r"(c[1])
        : "r"(a[0]), "r"(a[1]), "r"(a[2]), "r"(a[3]), "r"(b0), "r"(b1));
}

// ---------- prep kernels ----------
__global__ void prep_x(const float* __restrict__ in, fp16* __restrict__ xh) {
    __shared__ float tl[32][33];
    int t0 = blockIdx.x * 32, c0 = blockIdx.y * 32, b = blockIdx.z;
    int tx = threadIdx.x, ty = threadIdx.y;
    #pragma unroll
    for (int r = 0; r < 4; ++r)
        tl[ty + r * 8][tx] = in[((size_t)b * CCH + c0 + ty + r * 8) * TLEN + t0 + tx];
    __syncthreads();
    #pragma unroll
    for (int r = 0; r < 4; ++r) {
        int t = t0 + ty + r * 8;
        float v = tl[tx][ty + r * 8];
        size_t o = ((size_t)b * TLEN + t) * CCH + c0 + tx;
        xh[o] = __float2half(v);
    }
}

__global__ void prep_wc(const float* __restrict__ w, fp16* __restrict__ wa) {
    size_t i = (size_t)blockIdx.x * 256 + threadIdx.x;
    if (i >= (size_t)NLAYER * 2 * 24 * 2 * 8192) return;
    int e = (int)(i & 8191);
    int tile = (int)(i >> 13);
    int half = tile & 1;
    int chunk = (tile >> 1) % 24;
    int lg = (tile >> 1) / 24;
    int g = lg & 1, l = lg >> 1;
    int row = e >> 5, k = e & 31;
    int o = (row < 128) ? g * 128 + row : 128 + g * 128 + row;
    int tap = chunk >> 3;
    int c = (chunk & 7) * 32 + k;
    float v = w[(((size_t)l * 512 + o) * 256 + c) * 3 + tap];
    fp16 hi = __float2half(v);
    fp16 val = half ? __float2half(v - __half2float(hi)) : hi;
    wa[(size_t)tile * 8192 + (swz64(row * 64 + k * 2) >> 1)] = val;
}

__global__ void prep_wo(const float* __restrict__ w, fp16* __restrict__ wa) {
    size_t i = (size_t)blockIdx.x * 256 + threadIdx.x;
    if (i >= (size_t)NLAYER * 8 * 2 * 8192) return;
    int e = (int)(i & 8191);
    int tile = (int)(i >> 13);
    int half = tile & 1;
    int chunk = (tile >> 1) & 7;
    int l = (tile >> 1) >> 3;
    int row = e >> 5, k = e & 31;
    int c = chunk * 32 + k;
    float v = w[((size_t)l * 256 + row) * 256 + c];
    fp16 hi = __float2half(v);
    fp16 val = half ? __float2half(v - __half2float(hi)) : hi;
    wa[(size_t)tile * 8192 + (swz64(row * 64 + k * 2) >> 1)] = val;
}

// ---------- per-chunk compute: warp tile 32t x 64o, K=32, 2-term ----------
// stage layout: Whi @0 (16KB), Wlo @16384 (16KB), Xhi @32768 (4KB)
__device__ __forceinline__ void compute_stage(
    uint32_t SS, int tg, int oq, int lane,
    float acc[2][8][4], uint32_t acc16[2][8][2])
{
    uint32_t Xb = SS + 32768;
    #pragma unroll
    for (int kk = 0; kk < 2; ++kk) {
        uint32_t Ah[2][4];
        int aseg = 2 * kk + (lane >> 4);
        #pragma unroll
        for (int mt = 0; mt < 2; ++mt) {
            int r = tg * 32 + mt * 16 + (lane & 15);
            uint32_t aa = Xb + r * 64 + ((uint32_t)(aseg ^ ((r >> 1) & 3)) << 4);
            ldsm4(Ah[mt][0], Ah[mt][1], Ah[mt][2], Ah[mt][3], aa);
        }
        #pragma unroll
        for (int np = 0; np < 4; ++np) {
            int br = oq * 64 + np * 16 + ((lane >> 4) << 3) + (lane & 7);
            int bseg = 2 * kk + ((lane >> 3) & 1);
            uint32_t ba = SS + br * 64 + ((uint32_t)(bseg ^ ((br >> 1) & 3)) << 4);
            uint32_t bh0, bh1, bh2, bh3, bl0, bl1, bl2, bl3;
            ldsm4(bh0, bh1, bh2, bh3, ba);
            ldsm4(bl0, bl1, bl2, bl3, ba + 16384);
            #pragma unroll
            for (int mt = 0; mt < 2; ++mt) {
                mma_f32(acc[mt][2 * np],     Ah[mt], bh0, bh1);
                mma_f32(acc[mt][2 * np + 1], Ah[mt], bh2, bh3);
                mma_f16(acc16[mt][2 * np],     Ah[mt], bl0, bl1);
                mma_f16(acc16[mt][2 * np + 1], Ah[mt], bl2, bl3);
            }
        }
    }
}

__device__ __forceinline__ void merge_corr(float acc[2][8][4], uint32_t acc16[2][8][2]) {
    #pragma unroll
    for (int mt = 0; mt < 2; ++mt)
        #pragma unroll
        for (int nt = 0; nt < 8; ++nt) {
            float2 p0 = __half22float2(*(__half2*)&acc16[mt][nt][0]);
            float2 p1 = __half22float2(*(__half2*)&acc16[mt][nt][1]);
            acc[mt][nt][0] += p0.x;
            acc[mt][nt][1] += p0.y;
            acc[mt][nt][2] += p1.x;
            acc[mt][nt][3] += p1.y;
        }
}

// ---------- conv layer kernel: CTA = 64t x 256o, 24 K-chunks of 32 ----------
__global__ __launch_bounds__(256, 2) void conv_k(
    const fp16* __restrict__ xh,
    const fp16* __restrict__ wA, const float* __restrict__ bconv,
    const float* __restrict__ xres, float* __restrict__ skip,
    fp16* __restrict__ hh,
    float* __restrict__ xout, int dil, int last)
{
    extern __shared__ char sm[];
    uint32_t sbd = s2u(sm);
    int tid = threadIdx.x, lane = tid & 31, wid = tid >> 5;
    int g = blockIdx.y;
    int b = blockIdx.x >> 7, t0 = (blockIdx.x & 127) << 6;
    int tg = wid & 1, oq = wid >> 1;
    const char* xhB = (const char*)xh;

    auto load_chunk = [&](int c, int s) {
        uint32_t SS = sbd + s * STGB;
        const char* wsrc = (const char*)(wA + ((size_t)(g * 24 + c)) * 16384);
        #pragma unroll
        for (int it = 0; it < 8; ++it) {
            uint32_t off = it * 4096 + tid * 16;
            cpa16(SS + off, wsrc + off);
        }
        int tap = c >> 3, kq = c & 7;
        int tt = tid >> 2, sg = tid & 3;
        int ts = t0 + tt - dil * (2 - tap);
        uint32_t pr = ts >= 0 ? 16u : 0u;
        size_t gb = (size_t)(b * TLEN + (ts < 0 ? 0 : ts)) * 512 + kq * 64;
        uint32_t dst = SS + 32768 + tt * 64 + ((uint32_t)(sg ^ ((tt >> 1) & 3)) << 4);
        cpa16z(dst, xhB + gb + sg * 16, pr);
        CPC();
    };

    float acc[2][8][4];
    uint32_t acc16[2][8][2];
    #pragma unroll
    for (int a = 0; a < 2; ++a)
        #pragma unroll
        for (int n = 0; n < 8; ++n) {
            #pragma unroll
            for (int q = 0; q < 4; ++q) acc[a][n][q] = 0.0f;
            acc16[a][n][0] = 0u; acc16[a][n][1] = 0u;
        }

    load_chunk(0, 0);
    for (int c = 0; c < 24; ++c) {
        int s = c & 1;
        asm volatile("cp.async.wait_group 0;" ::: "memory");
        __syncthreads();
        if (c + 1 < 24) load_chunk(c + 1, 1 - s);
        compute_stage(sbd + s * STGB, tg, oq, lane, acc, acc16);
    }
    merge_corr(acc, acc16);
    __syncthreads();

    // ---- epilogue ----
    float* zb = (float*)sm;
    #pragma unroll
    for (int mt = 0; mt < 2; ++mt)
        #pragma unroll
        for (int nt = 0; nt < 8; ++nt) {
            int t = tg * 32 + mt * 16 + (lane >> 2);
            int o = oq * 64 + nt * 8 + (lane & 3) * 2;
            *(float2*)&zb[t * 260 + o]       = make_float2(acc[mt][nt][0], acc[mt][nt][1]);
            *(float2*)&zb[(t + 8) * 260 + o] = make_float2(acc[mt][nt][2], acc[mt][nt][3]);
        }
    __syncthreads();
    for (int i = tid; i < 64 * 32; i += 256) {
        int t = i >> 5, c0 = (i & 31) * 4;
        #pragma unroll
        for (int j = 0; j < 4; ++j) {
            float zt = zb[t * 260 + c0 + j];
            float zs = zb[t * 260 + 128 + c0 + j];
            float h = tanhf(zt + bconv[g * 128 + c0 + j]) *
                      sigf(zs + bconv[256 + g * 128 + c0 + j]);
            zb[t * 260 + c0 + j] = h;
        }
    }
    __syncthreads();
    for (int i = tid; i < 128 * 16; i += 256) {
        int o = i >> 4, sg = i & 15, t = sg * 4;
        float4 v;
        v.x = zb[(t + 0) * 260 + o];
        v.y = zb[(t + 1) * 260 + o];
        v.z = zb[(t + 2) * 260 + o];
        v.w = zb[(t + 3) * 260 + o];
        size_t go = ((size_t)(b * 256) + g * 128 + o) * TLEN + t0 + t;
        *(float4*)(skip + go) = v;
        if (last) {
            float4 xr = *(const float4*)(xres + go);
            float4 ov = make_float4(v.x + xr.x, v.y + xr.y, v.z + xr.z, v.w + xr.w);
            *(float4*)(xout + go) = ov;
        }
    }
    if (!last) {
        for (int i = tid; i < 64 * 32; i += 256) {
            int t = i >> 5, c0 = (i & 31) * 4;
            float v0 = zb[t * 260 + c0], v1 = zb[t * 260 + c0 + 1];
            float v2 = zb[t * 260 + c0 + 2], v3 = zb[t * 260 + c0 + 3];
            size_t gi = ((size_t)(b * TLEN) + t0 + t) * CCH + g * 128 + c0;
            ((__half2*)(hh + gi))[0] = __halves2half2(__float2half(v0), __float2half(v1));
            ((__half2*)(hh + gi))[1] = __halves2half2(__float2half(v2), __float2half(v3));
        }
    }
}

// ---------- 1x1 + residual layer: CTA = 64t x 256o, 8 K-chunks of 32 ----------
__global__ __launch_bounds__(256, 2) void out_k(
    const fp16* __restrict__ hh,
    const fp16* __restrict__ wA, const float* __restrict__ bout,
    const float* __restrict__ xres, float* __restrict__ xcm,
    fp16* __restrict__ xh)
{
    extern __shared__ char sm[];
    uint32_t sbd = s2u(sm);
    int tid = threadIdx.x, lane = tid & 31, wid = tid >> 5;
    int b = blockIdx.x >> 7, t0 = (blockIdx.x & 127) << 6;
    int tg = wid & 1, oq = wid >> 1;
    const char* hhB = (const char*)hh;

    auto load_chunk = [&](int c, int s) {
        uint32_t SS = sbd + s * STGB;
        const char* wsrc = (const char*)(wA + (size_t)c * 16384);
        #pragma unroll
        for (int it = 0; it < 8; ++it) {
            uint32_t off = it * 4096 + tid * 16;
            cpa16(SS + off, wsrc + off);
        }
        int tt = tid >> 2, sg = tid & 3;
        size_t gb = (size_t)(b * TLEN + t0 + tt) * 512 + c * 64;
        uint32_t dst = SS + 32768 + tt * 64 + ((uint32_t)(sg ^ ((tt >> 1) & 3)) << 4);
        cpa16(dst, hhB + gb + sg * 16);
        CPC();
    };

    float acc[2][8][4];
    uint32_t acc16[2][8][2];
    #pragma unroll
    for (int a = 0; a < 2; ++a)
        #pragma unroll
        for (int n = 0; n < 8; ++n) {
            #pragma unroll
            for (int q = 0; q < 4; ++q) acc[a][n][q] = 0.0f;
            acc16[a][n][0] = 0u; acc16[a][n][1] = 0u;
        }

    load_chunk(0, 0);
    for (int c = 0; c < 8; ++c) {
        int s = c & 1;
        asm volatile("cp.async.wait_group 0;" ::: "memory");
        __syncthreads();
        if (c + 1 < 8) load_chunk(c + 1, 1 - s);
        compute_stage(sbd + s * STGB, tg, oq, lane, acc, acc16);
    }
    merge_corr(acc, acc16);
    __syncthreads();

    float* zb = (float*)sm;
    #pragma unroll
    for (int mt = 0; mt < 2; ++mt)
        #pragma unroll
        for (int nt = 0; nt < 8; ++nt) {
            int t = tg * 32 + mt * 16 + (lane >> 2);
            int o = oq * 64 + nt * 8 + (lane & 3) * 2;
            *(float2*)&zb[t * 260 + o]       = make_float2(acc[mt][nt][0], acc[mt][nt][1]);
            *(float2*)&zb[(t + 8) * 260 + o] = make_float2(acc[mt][nt][2], acc[mt][nt][3]);
        }
    __syncthreads();
    for (int i = tid; i < 256 * 16; i += 256) {
        int o = i >> 4, sg = i & 15, t = sg * 4;
        size_t go = ((size_t)(b * 256) + o) * TLEN + t0 + t;
        float4 xr = *(const float4*)(xres + go);
        float bo = bout[o];
        float4 v;
        v.x = zb[(t + 0) * 260 + o] + bo + xr.x;
        v.y = zb[(t + 1) * 260 + o] + bo + xr.y;
        v.z = zb[(t + 2) * 260 + o] + bo + xr.z;
        v.w = zb[(t + 3) * 260 + o] + bo + xr.w;
        *(float4*)(xcm + go) = v;
        zb[(t + 0) * 260 + o] = v.x;
        zb[(t + 1) * 260 + o] = v.y;
        zb[(t + 2) * 260 + o] = v.z;
        zb[(t + 3) * 260 + o] = v.w;
    }
    __syncthreads();
    for (int i = tid; i < 64 * 64; i += 256) {
        int t = i >> 6, c0 = (i & 63) * 4;
        float v0 = zb[t * 260 + c0], v1 = zb[t * 260 + c0 + 1];
        float v2 = zb[t * 260 + c0 + 2], v3 = zb[t * 260 + c0 + 3];
        size_t gi = ((size_t)(b * TLEN) + t0 + t) * CCH + c0;
        ((__half2*)(xh + gi))[0] = __halves2half2(__float2half(v0), __float2half(v1));
        ((__half2*)(xh + gi))[1] = __halves2half2(__float2half(v2), __float2half(v3));
    }
}

// ---------- host ----------
extern "C" void kernel_launch(void* const* d_in, const int* in_sizes, int n_in,
                              void* d_out, int out_size) {
    const float* input = (const float*)d_in[0];
    const float* wconv = (const float*)d_in[1];
    const float* bconv = (const float*)d_in[2];
    const float* wout  = (const float*)d_in[3];
    const float* bout  = (const float*)d_in[4];
    float* out = (float*)d_out;

    fp16 *xh, *hh, *wcA, *woA; float* xcm;
    cudaGetSymbolAddress((void**)&xh, g_xh);
    cudaGetSymbolAddress((void**)&hh, g_hh);
    cudaGetSymbolAddress((void**)&xcm, g_xcm);
    cudaGetSymbolAddress((void**)&wcA, g_wcA);
    cudaGetSymbolAddress((void**)&woA, g_woA);

    cudaFuncSetAttribute(conv_k, cudaFuncAttributeMaxDynamicSharedMemorySize, SMEMB);
    cudaFuncSetAttribute(out_k,  cudaFuncAttributeMaxDynamicSharedMemorySize, SMEMB);

    prep_x<<<dim3(TLEN / 32, CCH / 32, BSZ), dim3(32, 8)>>>(input, xh);
    {
        size_t n = (size_t)NLAYER * 2 * 24 * 2 * 8192;
        prep_wc<<<(unsigned)((n + 255) / 256), 256>>>(wconv, wcA);
    }
    {
        size_t n = (size_t)NLAYER * 8 * 2 * 8192;
        prep_wo<<<(unsigned)((n + 255) / 256), 256>>>(wout, woA);
    }

    const size_t XE = (size_t)BSZ * CCH * TLEN;
    const int DIL[NLAYER] = {1, 2, 4, 8, 16, 32, 64, 128, 256, 512};

    for (int l = 0; l < NLAYER; ++l) {
        int last = (l == NLAYER - 1);
        conv_k<<<dim3(512, 2), 256, SMEMB>>>(
            xh, wcA + (size_t)l * 2 * 24 * 2 * 8192, bconv + l * 512,
            xcm, out + XE + (size_t)l * XE, hh, out, DIL[l], last);
        if (!last) {
            out_k<<<512, 256, SMEMB>>>(
                hh, woA + (size_t)l * 8 * 2 * 8192, bout + l * 256,
                (l == 0) ? input : xcm, xcm, xh);
        }
    }
    (void)in_sizes; (void)n_in; (void)out_size;
}